// round 9
// baseline (speedup 1.0000x reference)
#include <cuda_runtime.h>
#include <cuda_fp16.h>
#include <math.h>
#include <stdint.h>
#include <stddef.h>

#define B_ 16
#define C_ 512
#define N_ 4096
#define NROWS (B_*C_)

#define TM 128
#define TN 128
#define TKC 64                            // K per chunk (doubled)

#define A_PAD 72                          // 64 + 8 halves
#define B_PAD_T 136
#define AH_BYTES (128*72*2)               // 18432
#define BH_BYTES 18432                    // max(128*72*2, 64*136*2)
#define STG_BYTES (AH_BYTES + BH_BYTES)   // 36864
#define NSTAGE 3
#define SMEM_TOTAL (NSTAGE*STG_BYTES)     // 110592

// ---------------- scratch (device globals, all fp16) ----------------
__device__ __half g_qkvh[(size_t)B_*3*C_*N_];
__device__ __half g_s  [(size_t)B_*2*C_*N_];    // {-relu(q*mq) | relu(k*mk)}
__device__ __half g_qh [(size_t)B_*C_*N_];
__device__ __half g_yh [(size_t)B_*C_*N_];
__device__ __half g_gph[(size_t)B_*C_*N_];
__device__ __half g_at [(size_t)B_*C_*C_];
__device__ __half g_xh [(size_t)B_*C_*N_];
__device__ __half g_wqkv[3*C_*C_];
__device__ __half g_wm[2*C_*C_];
__device__ __half g_wg[C_*2*C_];
__device__ __half g_wr[C_*C_];

// ---------------- PTX helpers (portable) ----------------
__device__ __forceinline__ void cpa16(uint32_t dst, const void* src){
    asm volatile("cp.async.cg.shared.global [%0], [%1], 16;"
                 :: "r"(dst), "l"(src) : "memory");
}
__device__ __forceinline__ void cp_commit(){
    asm volatile("cp.async.commit_group;" ::: "memory");
}
__device__ __forceinline__ void cp_wait1(){
    asm volatile("cp.async.wait_group 1;" ::: "memory");
}
__device__ __forceinline__ void cp_wait0(){
    asm volatile("cp.async.wait_group 0;" ::: "memory");
}
__device__ __forceinline__ uint32_t smem_u32(const void* p){
    uint32_t a;
    asm("{ .reg .u64 t; cvta.to.shared.u64 t, %1; cvt.u32.u64 %0, t; }"
        : "=r"(a) : "l"(p));
    return a;
}
__device__ __forceinline__ void ldsm4(uint32_t* r, uint32_t addr){
    asm volatile("ldmatrix.sync.aligned.m8n8.x4.shared.b16 {%0,%1,%2,%3}, [%4];"
        : "=r"(r[0]), "=r"(r[1]), "=r"(r[2]), "=r"(r[3]) : "r"(addr));
}
__device__ __forceinline__ void ldsm2(uint32_t* r, uint32_t addr){
    asm volatile("ldmatrix.sync.aligned.m8n8.x2.shared.b16 {%0,%1}, [%2];"
        : "=r"(r[0]), "=r"(r[1]) : "r"(addr));
}
__device__ __forceinline__ void ldsm2t(uint32_t* r, uint32_t addr){
    asm volatile("ldmatrix.sync.aligned.m8n8.x2.trans.shared.b16 {%0,%1}, [%2];"
        : "=r"(r[0]), "=r"(r[1]) : "r"(addr));
}
__device__ __forceinline__ void mma16816(float* c, const uint32_t* a, const uint32_t* b){
    asm volatile(
        "mma.sync.aligned.m16n8k16.row.col.f32.f16.f16.f32 "
        "{%0,%1,%2,%3}, {%4,%5,%6,%7}, {%8,%9}, {%0,%1,%2,%3};"
        : "+f"(c[0]), "+f"(c[1]), "+f"(c[2]), "+f"(c[3])
        : "r"(a[0]), "r"(a[1]), "r"(a[2]), "r"(a[3]), "r"(b[0]), "r"(b[1]));
}
__device__ __forceinline__ uint32_t pack_h2(float x, float y){
    __half2 p(__float2half_rn(x), __float2half_rn(y));
    return *(uint32_t*)&p;
}
__device__ __forceinline__ float2 unpack_h2(uint32_t u){
    __half2 p = *(__half2*)&u;
    return make_float2(__half2float(p.x), __half2float(p.y));
}

// ---------------------------------------------------------------------------
// Pure fp16 GEMM, TKC=64 chunks, 3-stage cp.async pipeline (lookahead 2).
//   val = scale * sum_k A[m,k] * B[k,n] + bias[m]
// epiMode 0: fp32 Y rows m<y32Max; fp16 Yh rows >= yhOff.
// epiMode 1: Y(fp32) = Ey + sigmoid(Egp)*(val - Ey), Egp/Ey fp16.
// epiMode 2: prod = val * Eq[m,n];  Yh = (m<C_) ? -relu(prod) : relu(prod).
// ---------------------------------------------------------------------------
__global__ void __launch_bounds__(256, 2) mma_gemm(
    const __half* __restrict__ Ah, int lda, size_t aBatch,
    const __half* __restrict__ B1, size_t b1B,
    const __half* __restrict__ B2, size_t b2B, int K1,
    const float* __restrict__ bias, float scale,
    float* __restrict__ Y, size_t yB, int yStride, int y32Max,
    __half* __restrict__ Yh, size_t yhB, int yhOff,
    const __half* __restrict__ Egp, const __half* __restrict__ Ey,
    const __half* __restrict__ Eq, size_t eqB, int epiMode,
    int K, int transB)
{
    extern __shared__ char smem[];
    const uint32_t sbase = smem_u32(smem);

    const int tid  = threadIdx.x;
    const int lane = tid & 31;
    const int wid  = tid >> 5;
    const int wm   = wid & 1;
    const int wn   = wid >> 1;
    const int b    = blockIdx.z;
    const int m0   = blockIdx.y * TM;
    const int n0   = blockIdx.x * TN;

    const __half* Ab = Ah + (size_t)b * aBatch;
    const int NC = K / TKC;

    auto load_stage = [&](int s, int kc){
        const uint32_t sa = sbase + s * STG_BYTES;
        // A: 128 rows x 64 halves = 1024 x 16B
        #pragma unroll
        for (int it = 0; it < 4; it++){
            int slot = it * 256 + tid;
            int row = slot >> 3, c8 = (slot & 7) << 3;
            size_t go = (size_t)(m0 + row) * lda + kc * TKC + c8;
            cpa16(sa + 2 * (row * A_PAD + c8), Ab + go);
        }
        const uint32_t sb = sa + AH_BYTES;
        if (transB){
            // 64 k-rows x 128 n
            #pragma unroll
            for (int it = 0; it < 4; it++){
                int slot = it * 256 + tid;
                int k = slot >> 4, n8 = (slot & 15) << 3;
                int kg = kc * TKC + k;
                const __half* src = (kg < K1)
                    ? (B1 + (size_t)b * b1B + (size_t)kg * N_ + n0 + n8)
                    : (B2 + (size_t)b * b2B + (size_t)(kg - K1) * N_ + n0 + n8);
                cpa16(sb + 2 * (k * B_PAD_T + n8), src);
            }
        } else {
            // 128 n-rows x 64 k
            #pragma unroll
            for (int it = 0; it < 4; it++){
                int slot = it * 256 + tid;
                int n = slot >> 3, k8 = (slot & 7) << 3;
                size_t go = (size_t)b * b1B + (size_t)(n0 + n) * N_ + kc * TKC + k8;
                cpa16(sb + 2 * (n * A_PAD + k8), B1 + go);
            }
        }
        cp_commit();
    };

    float acc[4][4][4];
    #pragma unroll
    for (int i = 0; i < 4; i++)
        #pragma unroll
        for (int j = 0; j < 4; j++)
            #pragma unroll
            for (int r = 0; r < 4; r++) acc[i][j][r] = 0.f;

    const int a_lrow = lane & 15;
    const int a_lcol = (lane >> 4) << 3;
    const int bl_    = lane & 15;

    load_stage(0, 0);
    if (NC > 1) load_stage(1, 1);

    for (int kc = 0; kc < NC; kc++){
        if (kc + 1 < NC) cp_wait1(); else cp_wait0();
        __syncthreads();

        const uint32_t sa = sbase + (kc % NSTAGE) * STG_BYTES;
        const uint32_t sb = sa + AH_BYTES;

        #pragma unroll
        for (int ks = 0; ks < 4; ks++){
            uint32_t ah[4][4], bb[4][2];
            #pragma unroll
            for (int mt = 0; mt < 4; mt++){
                uint32_t ad = sa + 2 * ((wm*64 + mt*16 + a_lrow) * A_PAD + ks*16 + a_lcol);
                ldsm4(ah[mt], ad);
            }
            #pragma unroll
            for (int nt = 0; nt < 4; nt++){
                if (transB){
                    uint32_t bd = sb + 2 * ((ks*16 + bl_) * B_PAD_T + wn*32 + nt*8);
                    ldsm2t(bb[nt], bd);
                } else {
                    uint32_t bd = sb + 2 * ((wn*32 + nt*8 + (bl_ & 7)) * A_PAD + ks*16 + ((bl_ >> 3) << 3));
                    ldsm2(bb[nt], bd);
                }
            }
            #pragma unroll
            for (int mt = 0; mt < 4; mt++)
                #pragma unroll
                for (int nt = 0; nt < 4; nt++)
                    mma16816(acc[mt][nt], ah[mt], bb[nt]);
        }
        if (kc + 2 < NC) load_stage((kc + 2) % NSTAGE, kc + 2);
    }

    // ---- epilogue ----
    const int g = lane >> 2;
    const int t = lane & 3;
    #pragma unroll
    for (int mt = 0; mt < 4; mt++){
        int m = m0 + wm*64 + mt*16 + g;
        float bi_lo = bias ? bias[m]     : 0.f;
        float bi_hi = bias ? bias[m + 8] : 0.f;
        #pragma unroll
        for (int nt = 0; nt < 4; nt++){
            int nn = n0 + wn*32 + nt*8 + 2*t;
            float v00 = acc[mt][nt][0] * scale + bi_lo;
            float v01 = acc[mt][nt][1] * scale + bi_lo;
            float v10 = acc[mt][nt][2] * scale + bi_hi;
            float v11 = acc[mt][nt][3] * scale + bi_hi;

            if (epiMode == 1){
                size_t eo0 = (size_t)b * yhB + (size_t)m * N_ + nn;
                size_t eo1 = eo0 + (size_t)8 * N_;
                float2 gp0 = unpack_h2(*(const uint32_t*)(Egp + eo0));
                float2 gp1 = unpack_h2(*(const uint32_t*)(Egp + eo1));
                float2 y0  = unpack_h2(*(const uint32_t*)(Ey + eo0));
                float2 y1  = unpack_h2(*(const uint32_t*)(Ey + eo1));
                float s0 = 1.f/(1.f+__expf(-gp0.x));
                float s1 = 1.f/(1.f+__expf(-gp0.y));
                float s2 = 1.f/(1.f+__expf(-gp1.x));
                float s3 = 1.f/(1.f+__expf(-gp1.y));
                size_t off0 = (size_t)b * yB + (size_t)m * yStride + nn;
                size_t off1 = off0 + (size_t)8 * yStride;
                float2 o0, o1;
                o0.x = y0.x + s0 * (v00 - y0.x);
                o0.y = y0.y + s1 * (v01 - y0.y);
                o1.x = y1.x + s2 * (v10 - y1.x);
                o1.y = y1.y + s3 * (v11 - y1.y);
                *(float2*)(Y + off0) = o0;
                *(float2*)(Y + off1) = o1;
            } else if (epiMode == 2){
                size_t qo0 = (size_t)b * eqB + (size_t)m * N_ + nn;
                size_t qo1 = qo0 + (size_t)8 * N_;
                float2 q0 = unpack_h2(*(const uint32_t*)(Eq + qo0));
                float2 q1 = unpack_h2(*(const uint32_t*)(Eq + qo1));
                float p00 = v00 * q0.x, p01 = v01 * q0.y;
                float p10 = v10 * q1.x, p11 = v11 * q1.y;
                bool neg0 = (m < C_), neg1 = (m + 8 < C_);
                p00 = neg0 ? -fmaxf(p00, 0.f) : fmaxf(p00, 0.f);
                p01 = neg0 ? -fmaxf(p01, 0.f) : fmaxf(p01, 0.f);
                p10 = neg1 ? -fmaxf(p10, 0.f) : fmaxf(p10, 0.f);
                p11 = neg1 ? -fmaxf(p11, 0.f) : fmaxf(p11, 0.f);
                size_t so0 = (size_t)b * yhB + (size_t)m * N_ + nn;
                size_t so1 = so0 + (size_t)8 * N_;
                *(uint32_t*)(Yh + so0) = pack_h2(p00, p01);
                *(uint32_t*)(Yh + so1) = pack_h2(p10, p11);
            } else {
                if (Y && m < y32Max){
                    size_t off0 = (size_t)b * yB + (size_t)m * yStride + nn;
                    size_t off1 = off0 + (size_t)8 * yStride;
                    float2 o0 = {v00, v01}, o1 = {v10, v11};
                    *(float2*)(Y + off0) = o0;
                    *(float2*)(Y + off1) = o1;
                }
                if (Yh && m >= yhOff){
                    size_t so0 = (size_t)b * yhB + (size_t)(m - yhOff) * N_ + nn;
                    size_t so1 = so0 + (size_t)8 * N_;
                    *(uint32_t*)(Yh + so0) = pack_h2(v00, v01);
                    *(uint32_t*)(Yh + so1) = pack_h2(v10, v11);
                }
            }
        }
    }
}

// ---------------------------------------------------------------------------
__global__ void conv_h(const float* __restrict__ s, __half* __restrict__ h, int n)
{
    int i = blockIdx.x * 256 + threadIdx.x;
    if (i < n) h[i] = __float2half_rn(s[i]);
}

// ---------------------------------------------------------------------------
__global__ void softmax_q(const __half* __restrict__ tbuf, __half* __restrict__ qh)
{
    __shared__ float red[8];
    __shared__ float bc;
    const int row = blockIdx.x;
    const int b = row >> 9, c = row & 511;
    const uint32_t* src = (const uint32_t*)(tbuf + ((size_t)b*1024 + c) * (size_t)N_);
    uint32_t* dst = (uint32_t*)(qh + (size_t)row * N_);

    float v[16];
    float mx = -1e30f;
    #pragma unroll
    for (int i = 0; i < 8; i++){
        int idx = threadIdx.x + (i << 8);
        float2 f = unpack_h2(src[idx]);
        v[2*i]   = f.x;
        v[2*i+1] = f.y;
        mx = fmaxf(mx, fmaxf(f.x, f.y));
    }
    #pragma unroll
    for (int off = 16; off; off >>= 1)
        mx = fmaxf(mx, __shfl_xor_sync(0xffffffffu, mx, off));
    if ((threadIdx.x & 31) == 0) red[threadIdx.x >> 5] = mx;
    __syncthreads();
    if (threadIdx.x == 0){
        float tv = red[0];
        #pragma unroll
        for (int i = 1; i < 8; i++) tv = fmaxf(tv, red[i]);
        bc = tv;
    }
    __syncthreads();
    mx = bc;

    float sm = 0.f;
    #pragma unroll
    for (int i = 0; i < 16; i++){
        v[i] = __expf(v[i] - mx);
        sm += v[i];
    }
    #pragma unroll
    for (int off = 16; off; off >>= 1)
        sm += __shfl_xor_sync(0xffffffffu, sm, off);
    __syncthreads();
    if ((threadIdx.x & 31) == 0) red[threadIdx.x >> 5] = sm;
    __syncthreads();
    if (threadIdx.x == 0){
        float tv = 0.f;
        #pragma unroll
        for (int i = 0; i < 8; i++) tv += red[i];
        bc = tv;
    }
    __syncthreads();
    const float rinv = 1.f / bc;
    #pragma unroll
    for (int i = 0; i < 8; i++){
        int idx = threadIdx.x + (i << 8);
        dst[idx] = pack_h2(v[2*i] * rinv, v[2*i+1] * rinv);
    }
}

// ---------------------------------------------------------------------------
__global__ void softmax_attn(float* __restrict__ S, __half* __restrict__ ah)
{
    __shared__ float red[4];
    __shared__ float bc;
    const int row = blockIdx.x;
    float* p = S + (size_t)row * 512;
    const size_t base = (size_t)row * 512;

    float v[4];
    float mx = -1e30f;
    #pragma unroll
    for (int i = 0; i < 4; i++){
        int idx = threadIdx.x + (i << 7);
        v[i] = p[idx];
        mx = fmaxf(mx, v[i]);
    }
    #pragma unroll
    for (int off = 16; off; off >>= 1)
        mx = fmaxf(mx, __shfl_xor_sync(0xffffffffu, mx, off));
    if ((threadIdx.x & 31) == 0) red[threadIdx.x >> 5] = mx;
    __syncthreads();
    if (threadIdx.x == 0)
        bc = fmaxf(fmaxf(red[0], red[1]), fmaxf(red[2], red[3]));
    __syncthreads();
    mx = bc;

    float sm = 0.f;
    #pragma unroll
    for (int i = 0; i < 4; i++){
        v[i] = __expf(v[i] - mx);
        sm += v[i];
    }
    #pragma unroll
    for (int off = 16; off; off >>= 1)
        sm += __shfl_xor_sync(0xffffffffu, sm, off);
    __syncthreads();
    if ((threadIdx.x & 31) == 0) red[threadIdx.x >> 5] = sm;
    __syncthreads();
    if (threadIdx.x == 0) bc = red[0] + red[1] + red[2] + red[3];
    __syncthreads();
    const float rinv = 1.f / bc;
    #pragma unroll
    for (int i = 0; i < 4; i++){
        int idx = threadIdx.x + (i << 7);
        float f = v[i] * rinv;
        p[idx] = f;
        ah[base + idx] = __float2half_rn(f);
    }
}

// ---------------------------------------------------------------------------
extern "C" void kernel_launch(void* const* d_in, const int* in_sizes, int n_in,
                              void* d_out, int out_size)
{
    const float* x    = (const float*)d_in[0];
    const float* Wqkv = (const float*)d_in[1];
    const float* bqkv = (const float*)d_in[2];
    const float* Wm   = (const float*)d_in[3];
    const float* bm   = (const float*)d_in[4];
    const float* Wg   = (const float*)d_in[5];
    const float* bg   = (const float*)d_in[6];
    const float* Wr   = (const float*)d_in[7];
    const float* br   = (const float*)d_in[8];

    float* out  = (float*)d_out;
    float* attn = out + (size_t)B_ * C_ * N_;

    cudaFuncSetAttribute(mma_gemm, cudaFuncAttributeMaxDynamicSharedMemorySize, SMEM_TOTAL);

    __half *qkvh, *sbuf, *p_qh, *yh, *gph, *p_at, *xh;
    __half *wqkv, *wm, *wg, *wr;
    cudaGetSymbolAddress((void**)&qkvh, g_qkvh);
    cudaGetSymbolAddress((void**)&sbuf, g_s);
    cudaGetSymbolAddress((void**)&p_qh, g_qh);
    cudaGetSymbolAddress((void**)&yh,   g_yh);
    cudaGetSymbolAddress((void**)&gph,  g_gph);
    cudaGetSymbolAddress((void**)&p_at, g_at);
    cudaGetSymbolAddress((void**)&xh,   g_xh);
    cudaGetSymbolAddress((void**)&wqkv, g_wqkv);
    cudaGetSymbolAddress((void**)&wm,   g_wm);
    cudaGetSymbolAddress((void**)&wg,   g_wg);
    cudaGetSymbolAddress((void**)&wr,   g_wr);

    const size_t sBCN = (size_t)C_ * N_;
    const size_t s3CN = (size_t)3*C_ * N_;
    const size_t s2CN = (size_t)2*C_ * N_;

    // 0) convert weights and x to fp16
    conv_h<<<(3*C_*C_ + 255)/256, 256>>>(Wqkv, wqkv, 3*C_*C_);
    conv_h<<<(2*C_*C_ + 255)/256, 256>>>(Wm,   wm,   2*C_*C_);
    conv_h<<<(2*C_*C_ + 255)/256, 256>>>(Wg,   wg,   2*C_*C_);
    conv_h<<<(  C_*C_ + 255)/256, 256>>>(Wr,   wr,     C_*C_);
    conv_h<<<((int)(B_*sBCN) + 255)/256, 256>>>(x, xh, (int)(B_*sBCN));

    // 1) qkv = Wqkv @ x + bqkv  -> all fp16
    mma_gemm<<<dim3(N_/TN, 3*C_/TM, B_), 256, SMEM_TOTAL>>>(
        wqkv, C_, 0,
        xh, sBCN, nullptr, 0, C_,
        bqkv, 1.f, nullptr, 0, 0, 0,
        qkvh, s3CN, 0,
        nullptr, nullptr, nullptr, 0, 0, C_, 1);

    // 2) mqk = Wm @ v + bm ; epilogue 2 -> g_s = {-relu(q*mq) | relu(k*mk)}
    mma_gemm<<<dim3(N_/TN, 2*C_/TM, B_), 256, SMEM_TOTAL>>>(
        wm, C_, 0,
        qkvh + (size_t)2*C_*N_, s3CN, nullptr, 0, C_,
        bm, 1.f, nullptr, 0, 0, 0,
        sbuf, s2CN, 0,
        nullptr, nullptr, qkvh, s3CN, 2, C_, 1);

    // 3) _q = softmax over g_s rows 0..C -> fp16 qh
    softmax_q<<<NROWS, 256>>>(sbuf, p_qh);

    // 4) scores = _q @ _k^T / sqrt(C)  (NT, K=4096)
    mma_gemm<<<dim3(C_/TN, C_/TM, B_), 256, SMEM_TOTAL>>>(
        p_qh, N_, sBCN,
        sbuf + (size_t)C_*N_, s2CN, nullptr, 0, N_,
        nullptr, 1.0f/sqrtf((float)C_), attn, (size_t)C_*C_, C_, C_,
        nullptr, 0, 0,
        nullptr, nullptr, nullptr, 0, 0, N_, 0);

    // 5) attn = softmax(scores) in-place + fp16 copy
    softmax_attn<<<NROWS, 128>>>(attn, p_at);

    // 6) y = attn @ v -> fp16 yh
    mma_gemm<<<dim3(N_/TN, C_/TM, B_), 256, SMEM_TOTAL>>>(
        p_at, C_, (size_t)C_*C_,
        qkvh + (size_t)2*C_*N_, s3CN, nullptr, 0, C_,
        nullptr, 1.f, nullptr, 0, 0, 0,
        yh, sBCN, 0,
        nullptr, nullptr, nullptr, 0, 0, C_, 1);

    // 7) gpre = Wg @ [y; x] + bg -> fp16 gph
    mma_gemm<<<dim3(N_/TN, C_/TM, B_), 256, SMEM_TOTAL>>>(
        wg, 2*C_, 0,
        yh, sBCN, xh, sBCN, C_,
        bg, 1.f, nullptr, 0, 0, 0,
        gph, sBCN, 0,
        nullptr, nullptr, nullptr, 0, 0, 2*C_, 1);

    // 8) r = Wr @ x + br ; out = y + sigmoid(gp)*(r - y)
    mma_gemm<<<dim3(N_/TN, C_/TM, B_), 256, SMEM_TOTAL>>>(
        wr, C_, 0,
        xh, sBCN, nullptr, 0, C_,
        br, 1.f, out, sBCN, N_, C_,
        nullptr, sBCN, 0,
        gph, yh, nullptr, 0, 1, C_, 1);
}

// round 10
// speedup vs baseline: 1.2814x; 1.2814x over previous
#include <cuda_runtime.h>
#include <cuda_fp16.h>
#include <math.h>
#include <stdint.h>
#include <stddef.h>

#define B_ 16
#define C_ 512
#define N_ 4096
#define NROWS (B_*C_)

#define TM 128
#define TN 256                            // CTA tile N (doubled)
#define TKC 32

#define A_PAD 40
#define B_PAD_T 264                       // 256 + 8 halves
#define AH_BYTES (128*40*2)               // 10240
#define BH_BYTES 20480                    // max(256*40*2, 32*264*2=16896)
#define STG_BYTES (AH_BYTES + BH_BYTES)   // 30720
#define NSTAGE 4
#define SMEM_TOTAL (NSTAGE*STG_BYTES)     // 122880

// ---------------- scratch (device globals, all fp16) ----------------
__device__ __half g_qkvh[(size_t)B_*3*C_*N_];
__device__ __half g_s  [(size_t)B_*2*C_*N_];    // {-relu(q*mq) | relu(k*mk)}
__device__ __half g_qh [(size_t)B_*C_*N_];
__device__ __half g_yh [(size_t)B_*C_*N_];
__device__ __half g_gph[(size_t)B_*C_*N_];
__device__ __half g_at [(size_t)B_*C_*C_];
__device__ __half g_xh [(size_t)B_*C_*N_];
__device__ __half g_wqkv[3*C_*C_];
__device__ __half g_wm[2*C_*C_];
__device__ __half g_wg[C_*2*C_];
__device__ __half g_wr[C_*C_];

// ---------------- PTX helpers (portable) ----------------
__device__ __forceinline__ void cpa16(uint32_t dst, const void* src){
    asm volatile("cp.async.cg.shared.global [%0], [%1], 16;"
                 :: "r"(dst), "l"(src) : "memory");
}
__device__ __forceinline__ void cp_commit(){
    asm volatile("cp.async.commit_group;" ::: "memory");
}
__device__ __forceinline__ void cp_wait2(){
    asm volatile("cp.async.wait_group 2;" ::: "memory");
}
__device__ __forceinline__ void cp_wait1(){
    asm volatile("cp.async.wait_group 1;" ::: "memory");
}
__device__ __forceinline__ void cp_wait0(){
    asm volatile("cp.async.wait_group 0;" ::: "memory");
}
__device__ __forceinline__ uint32_t smem_u32(const void* p){
    uint32_t a;
    asm("{ .reg .u64 t; cvta.to.shared.u64 t, %1; cvt.u32.u64 %0, t; }"
        : "=r"(a) : "l"(p));
    return a;
}
__device__ __forceinline__ void ldsm4(uint32_t* r, uint32_t addr){
    asm volatile("ldmatrix.sync.aligned.m8n8.x4.shared.b16 {%0,%1,%2,%3}, [%4];"
        : "=r"(r[0]), "=r"(r[1]), "=r"(r[2]), "=r"(r[3]) : "r"(addr));
}
__device__ __forceinline__ void ldsm2(uint32_t* r, uint32_t addr){
    asm volatile("ldmatrix.sync.aligned.m8n8.x2.shared.b16 {%0,%1}, [%2];"
        : "=r"(r[0]), "=r"(r[1]) : "r"(addr));
}
__device__ __forceinline__ void ldsm2t(uint32_t* r, uint32_t addr){
    asm volatile("ldmatrix.sync.aligned.m8n8.x2.trans.shared.b16 {%0,%1}, [%2];"
        : "=r"(r[0]), "=r"(r[1]) : "r"(addr));
}
__device__ __forceinline__ void mma16816(float* c, const uint32_t* a, const uint32_t* b){
    asm volatile(
        "mma.sync.aligned.m16n8k16.row.col.f32.f16.f16.f32 "
        "{%0,%1,%2,%3}, {%4,%5,%6,%7}, {%8,%9}, {%0,%1,%2,%3};"
        : "+f"(c[0]), "+f"(c[1]), "+f"(c[2]), "+f"(c[3])
        : "r"(a[0]), "r"(a[1]), "r"(a[2]), "r"(a[3]), "r"(b[0]), "r"(b[1]));
}
__device__ __forceinline__ uint32_t pack_h2(float x, float y){
    __half2 p(__float2half_rn(x), __float2half_rn(y));
    return *(uint32_t*)&p;
}
__device__ __forceinline__ float2 unpack_h2(uint32_t u){
    __half2 p = *(__half2*)&u;
    return make_float2(__half2float(p.x), __half2float(p.y));
}

// ---------------------------------------------------------------------------
// Pure fp16 GEMM, CTA tile 128x256, warp tile 64x64 (2Mx4N warps),
// TKC=32, 4-stage cp.async pipeline.
//   val = scale * sum_k A[m,k] * B[k,n] + bias[m]
// epiMode 0: fp32 Y rows m<y32Max; fp16 Yh rows >= yhOff.
// epiMode 1: Y(fp32) = Ey + sigmoid(Egp)*(val - Ey), Egp/Ey fp16.
// epiMode 2: prod = val * Eq[m,n];  Yh = (m<C_) ? -relu(prod) : relu(prod).
// ---------------------------------------------------------------------------
__global__ void __launch_bounds__(256, 1) mma_gemm(
    const __half* __restrict__ Ah, int lda, size_t aBatch,
    const __half* __restrict__ B1, size_t b1B,
    const __half* __restrict__ B2, size_t b2B, int K1,
    const float* __restrict__ bias, float scale,
    float* __restrict__ Y, size_t yB, int yStride, int y32Max,
    __half* __restrict__ Yh, size_t yhB, int yhOff,
    const __half* __restrict__ Egp, const __half* __restrict__ Ey,
    const __half* __restrict__ Eq, size_t eqB, int epiMode,
    int K, int transB)
{
    extern __shared__ char smem[];
    const uint32_t sbase = smem_u32(smem);

    const int tid  = threadIdx.x;
    const int lane = tid & 31;
    const int wid  = tid >> 5;
    const int wm   = wid & 1;        // 0..1 (M strips of 64)
    const int wn   = wid >> 1;       // 0..3 (N strips of 64)
    const int b    = blockIdx.z;
    const int m0   = blockIdx.y * TM;
    const int n0   = blockIdx.x * TN;

    const __half* Ab = Ah + (size_t)b * aBatch;
    const int NC = K / TKC;

    auto load_stage = [&](int s, int kc){
        const uint32_t sa = sbase + s * STG_BYTES;
        // A: 128 rows x 32 halves = 512 x 16B -> 2 iters
        #pragma unroll
        for (int it = 0; it < 2; it++){
            int slot = it * 256 + tid;
            int row = slot >> 2, c8 = (slot & 3) << 3;
            size_t go = (size_t)(m0 + row) * lda + kc * TKC + c8;
            cpa16(sa + 2 * (row * A_PAD + c8), Ab + go);
        }
        const uint32_t sb = sa + AH_BYTES;
        if (transB){
            // 32 k-rows x 256 n = 1024 x 16B -> 4 iters
            #pragma unroll
            for (int it = 0; it < 4; it++){
                int slot = it * 256 + tid;
                int k = slot >> 5, n8 = (slot & 31) << 3;
                int kg = kc * TKC + k;
                const __half* src = (kg < K1)
                    ? (B1 + (size_t)b * b1B + (size_t)kg * N_ + n0 + n8)
                    : (B2 + (size_t)b * b2B + (size_t)(kg - K1) * N_ + n0 + n8);
                cpa16(sb + 2 * (k * B_PAD_T + n8), src);
            }
        } else {
            // 256 n-rows x 32 k = 1024 x 16B -> 4 iters
            #pragma unroll
            for (int it = 0; it < 4; it++){
                int slot = it * 256 + tid;
                int n = slot >> 2, k8 = (slot & 3) << 3;
                size_t go = (size_t)b * b1B + (size_t)(n0 + n) * N_ + kc * TKC + k8;
                cpa16(sb + 2 * (n * A_PAD + k8), B1 + go);
            }
        }
        cp_commit();
    };

    float acc[4][8][4];
    #pragma unroll
    for (int i = 0; i < 4; i++)
        #pragma unroll
        for (int j = 0; j < 8; j++)
            #pragma unroll
            for (int r = 0; r < 4; r++) acc[i][j][r] = 0.f;

    const int a_lrow = lane & 15;
    const int a_lcol = (lane >> 4) << 3;
    const int bl_    = lane & 15;

    load_stage(0, 0);
    if (NC > 1) load_stage(1, 1);
    if (NC > 2) load_stage(2, 2);

    for (int kc = 0; kc < NC; kc++){
        int pend = (NC - kc > 3) ? 3 : (NC - kc);
        if (pend == 3) cp_wait2();
        else if (pend == 2) cp_wait1();
        else cp_wait0();
        __syncthreads();

        const uint32_t sa = sbase + (kc % NSTAGE) * STG_BYTES;
        const uint32_t sb = sa + AH_BYTES;

        #pragma unroll
        for (int ks = 0; ks < 2; ks++){
            uint32_t ah[4][4], bb[8][2];
            #pragma unroll
            for (int mt = 0; mt < 4; mt++){
                uint32_t ad = sa + 2 * ((wm*64 + mt*16 + a_lrow) * A_PAD + ks*16 + a_lcol);
                ldsm4(ah[mt], ad);
            }
            #pragma unroll
            for (int nt = 0; nt < 8; nt++){
                if (transB){
                    uint32_t bd = sb + 2 * ((ks*16 + bl_) * B_PAD_T + wn*64 + nt*8);
                    ldsm2t(bb[nt], bd);
                } else {
                    uint32_t bd = sb + 2 * ((wn*64 + nt*8 + (bl_ & 7)) * A_PAD + ks*16 + ((bl_ >> 3) << 3));
                    ldsm2(bb[nt], bd);
                }
            }
            #pragma unroll
            for (int mt = 0; mt < 4; mt++)
                #pragma unroll
                for (int nt = 0; nt < 8; nt++)
                    mma16816(acc[mt][nt], ah[mt], bb[nt]);
        }
        if (kc + 3 < NC) load_stage((kc + 3) % NSTAGE, kc + 3);
    }

    // ---- epilogue ----
    const int g = lane >> 2;
    const int t = lane & 3;
    #pragma unroll
    for (int mt = 0; mt < 4; mt++){
        int m = m0 + wm*64 + mt*16 + g;
        float bi_lo = bias ? bias[m]     : 0.f;
        float bi_hi = bias ? bias[m + 8] : 0.f;
        #pragma unroll
        for (int nt = 0; nt < 8; nt++){
            int nn = n0 + wn*64 + nt*8 + 2*t;
            float v00 = acc[mt][nt][0] * scale + bi_lo;
            float v01 = acc[mt][nt][1] * scale + bi_lo;
            float v10 = acc[mt][nt][2] * scale + bi_hi;
            float v11 = acc[mt][nt][3] * scale + bi_hi;

            if (epiMode == 1){
                size_t eo0 = (size_t)b * yhB + (size_t)m * N_ + nn;
                size_t eo1 = eo0 + (size_t)8 * N_;
                float2 gp0 = unpack_h2(*(const uint32_t*)(Egp + eo0));
                float2 gp1 = unpack_h2(*(const uint32_t*)(Egp + eo1));
                float2 y0  = unpack_h2(*(const uint32_t*)(Ey + eo0));
                float2 y1  = unpack_h2(*(const uint32_t*)(Ey + eo1));
                float s0 = 1.f/(1.f+__expf(-gp0.x));
                float s1 = 1.f/(1.f+__expf(-gp0.y));
                float s2 = 1.f/(1.f+__expf(-gp1.x));
                float s3 = 1.f/(1.f+__expf(-gp1.y));
                size_t off0 = (size_t)b * yB + (size_t)m * yStride + nn;
                size_t off1 = off0 + (size_t)8 * yStride;
                float2 o0, o1;
                o0.x = y0.x + s0 * (v00 - y0.x);
                o0.y = y0.y + s1 * (v01 - y0.y);
                o1.x = y1.x + s2 * (v10 - y1.x);
                o1.y = y1.y + s3 * (v11 - y1.y);
                *(float2*)(Y + off0) = o0;
                *(float2*)(Y + off1) = o1;
            } else if (epiMode == 2){
                size_t qo0 = (size_t)b * eqB + (size_t)m * N_ + nn;
                size_t qo1 = qo0 + (size_t)8 * N_;
                float2 q0 = unpack_h2(*(const uint32_t*)(Eq + qo0));
                float2 q1 = unpack_h2(*(const uint32_t*)(Eq + qo1));
                float p00 = v00 * q0.x, p01 = v01 * q0.y;
                float p10 = v10 * q1.x, p11 = v11 * q1.y;
                bool neg0 = (m < C_), neg1 = (m + 8 < C_);
                p00 = neg0 ? -fmaxf(p00, 0.f) : fmaxf(p00, 0.f);
                p01 = neg0 ? -fmaxf(p01, 0.f) : fmaxf(p01, 0.f);
                p10 = neg1 ? -fmaxf(p10, 0.f) : fmaxf(p10, 0.f);
                p11 = neg1 ? -fmaxf(p11, 0.f) : fmaxf(p11, 0.f);
                size_t so0 = (size_t)b * yhB + (size_t)m * N_ + nn;
                size_t so1 = so0 + (size_t)8 * N_;
                *(uint32_t*)(Yh + so0) = pack_h2(p00, p01);
                *(uint32_t*)(Yh + so1) = pack_h2(p10, p11);
            } else {
                if (Y && m < y32Max){
                    size_t off0 = (size_t)b * yB + (size_t)m * yStride + nn;
                    size_t off1 = off0 + (size_t)8 * yStride;
                    float2 o0 = {v00, v01}, o1 = {v10, v11};
                    *(float2*)(Y + off0) = o0;
                    *(float2*)(Y + off1) = o1;
                }
                if (Yh && m >= yhOff){
                    size_t so0 = (size_t)b * yhB + (size_t)(m - yhOff) * N_ + nn;
                    size_t so1 = so0 + (size_t)8 * N_;
                    *(uint32_t*)(Yh + so0) = pack_h2(v00, v01);
                    *(uint32_t*)(Yh + so1) = pack_h2(v10, v11);
                }
            }
        }
    }
}

// ---------------------------------------------------------------------------
__global__ void conv_h(const float* __restrict__ s, __half* __restrict__ h, int n)
{
    int i = blockIdx.x * 256 + threadIdx.x;
    if (i < n) h[i] = __float2half_rn(s[i]);
}

// ---------------------------------------------------------------------------
__global__ void softmax_q(const __half* __restrict__ tbuf, __half* __restrict__ qh)
{
    __shared__ float red[8];
    __shared__ float bc;
    const int row = blockIdx.x;
    const int b = row >> 9, c = row & 511;
    const uint32_t* src = (const uint32_t*)(tbuf + ((size_t)b*1024 + c) * (size_t)N_);
    uint32_t* dst = (uint32_t*)(qh + (size_t)row * N_);

    float v[16];
    float mx = -1e30f;
    #pragma unroll
    for (int i = 0; i < 8; i++){
        int idx = threadIdx.x + (i << 8);
        float2 f = unpack_h2(src[idx]);
        v[2*i]   = f.x;
        v[2*i+1] = f.y;
        mx = fmaxf(mx, fmaxf(f.x, f.y));
    }
    #pragma unroll
    for (int off = 16; off; off >>= 1)
        mx = fmaxf(mx, __shfl_xor_sync(0xffffffffu, mx, off));
    if ((threadIdx.x & 31) == 0) red[threadIdx.x >> 5] = mx;
    __syncthreads();
    if (threadIdx.x == 0){
        float tv = red[0];
        #pragma unroll
        for (int i = 1; i < 8; i++) tv = fmaxf(tv, red[i]);
        bc = tv;
    }
    __syncthreads();
    mx = bc;

    float sm = 0.f;
    #pragma unroll
    for (int i = 0; i < 16; i++){
        v[i] = __expf(v[i] - mx);
        sm += v[i];
    }
    #pragma unroll
    for (int off = 16; off; off >>= 1)
        sm += __shfl_xor_sync(0xffffffffu, sm, off);
    __syncthreads();
    if ((threadIdx.x & 31) == 0) red[threadIdx.x >> 5] = sm;
    __syncthreads();
    if (threadIdx.x == 0){
        float tv = 0.f;
        #pragma unroll
        for (int i = 0; i < 8; i++) tv += red[i];
        bc = tv;
    }
    __syncthreads();
    const float rinv = 1.f / bc;
    #pragma unroll
    for (int i = 0; i < 8; i++){
        int idx = threadIdx.x + (i << 8);
        dst[idx] = pack_h2(v[2*i] * rinv, v[2*i+1] * rinv);
    }
}

// ---------------------------------------------------------------------------
__global__ void softmax_attn(float* __restrict__ S, __half* __restrict__ ah)
{
    __shared__ float red[4];
    __shared__ float bc;
    const int row = blockIdx.x;
    float* p = S + (size_t)row * 512;
    const size_t base = (size_t)row * 512;

    float v[4];
    float mx = -1e30f;
    #pragma unroll
    for (int i = 0; i < 4; i++){
        int idx = threadIdx.x + (i << 7);
        v[i] = p[idx];
        mx = fmaxf(mx, v[i]);
    }
    #pragma unroll
    for (int off = 16; off; off >>= 1)
        mx = fmaxf(mx, __shfl_xor_sync(0xffffffffu, mx, off));
    if ((threadIdx.x & 31) == 0) red[threadIdx.x >> 5] = mx;
    __syncthreads();
    if (threadIdx.x == 0)
        bc = fmaxf(fmaxf(red[0], red[1]), fmaxf(red[2], red[3]));
    __syncthreads();
    mx = bc;

    float sm = 0.f;
    #pragma unroll
    for (int i = 0; i < 4; i++){
        v[i] = __expf(v[i] - mx);
        sm += v[i];
    }
    #pragma unroll
    for (int off = 16; off; off >>= 1)
        sm += __shfl_xor_sync(0xffffffffu, sm, off);
    __syncthreads();
    if ((threadIdx.x & 31) == 0) red[threadIdx.x >> 5] = sm;
    __syncthreads();
    if (threadIdx.x == 0) bc = red[0] + red[1] + red[2] + red[3];
    __syncthreads();
    const float rinv = 1.f / bc;
    #pragma unroll
    for (int i = 0; i < 4; i++){
        int idx = threadIdx.x + (i << 7);
        float f = v[i] * rinv;
        p[idx] = f;
        ah[base + idx] = __float2half_rn(f);
    }
}

// ---------------------------------------------------------------------------
extern "C" void kernel_launch(void* const* d_in, const int* in_sizes, int n_in,
                              void* d_out, int out_size)
{
    const float* x    = (const float*)d_in[0];
    const float* Wqkv = (const float*)d_in[1];
    const float* bqkv = (const float*)d_in[2];
    const float* Wm   = (const float*)d_in[3];
    const float* bm   = (const float*)d_in[4];
    const float* Wg   = (const float*)d_in[5];
    const float* bg   = (const float*)d_in[6];
    const float* Wr   = (const float*)d_in[7];
    const float* br   = (const float*)d_in[8];

    float* out  = (float*)d_out;
    float* attn = out + (size_t)B_ * C_ * N_;

    cudaFuncSetAttribute(mma_gemm, cudaFuncAttributeMaxDynamicSharedMemorySize, SMEM_TOTAL);

    __half *qkvh, *sbuf, *p_qh, *yh, *gph, *p_at, *xh;
    __half *wqkv, *wm, *wg, *wr;
    cudaGetSymbolAddress((void**)&qkvh, g_qkvh);
    cudaGetSymbolAddress((void**)&sbuf, g_s);
    cudaGetSymbolAddress((void**)&p_qh, g_qh);
    cudaGetSymbolAddress((void**)&yh,   g_yh);
    cudaGetSymbolAddress((void**)&gph,  g_gph);
    cudaGetSymbolAddress((void**)&p_at, g_at);
    cudaGetSymbolAddress((void**)&xh,   g_xh);
    cudaGetSymbolAddress((void**)&wqkv, g_wqkv);
    cudaGetSymbolAddress((void**)&wm,   g_wm);
    cudaGetSymbolAddress((void**)&wg,   g_wg);
    cudaGetSymbolAddress((void**)&wr,   g_wr);

    const size_t sBCN = (size_t)C_ * N_;
    const size_t s3CN = (size_t)3*C_ * N_;
    const size_t s2CN = (size_t)2*C_ * N_;

    // 0) convert weights and x to fp16
    conv_h<<<(3*C_*C_ + 255)/256, 256>>>(Wqkv, wqkv, 3*C_*C_);
    conv_h<<<(2*C_*C_ + 255)/256, 256>>>(Wm,   wm,   2*C_*C_);
    conv_h<<<(2*C_*C_ + 255)/256, 256>>>(Wg,   wg,   2*C_*C_);
    conv_h<<<(  C_*C_ + 255)/256, 256>>>(Wr,   wr,     C_*C_);
    conv_h<<<((int)(B_*sBCN) + 255)/256, 256>>>(x, xh, (int)(B_*sBCN));

    // 1) qkv = Wqkv @ x + bqkv  -> all fp16
    mma_gemm<<<dim3(N_/TN, 3*C_/TM, B_), 256, SMEM_TOTAL>>>(
        wqkv, C_, 0,
        xh, sBCN, nullptr, 0, C_,
        bqkv, 1.f, nullptr, 0, 0, 0,
        qkvh, s3CN, 0,
        nullptr, nullptr, nullptr, 0, 0, C_, 1);

    // 2) mqk = Wm @ v + bm ; epilogue 2 -> g_s = {-relu(q*mq) | relu(k*mk)}
    mma_gemm<<<dim3(N_/TN, 2*C_/TM, B_), 256, SMEM_TOTAL>>>(
        wm, C_, 0,
        qkvh + (size_t)2*C_*N_, s3CN, nullptr, 0, C_,
        bm, 1.f, nullptr, 0, 0, 0,
        sbuf, s2CN, 0,
        nullptr, nullptr, qkvh, s3CN, 2, C_, 1);

    // 3) _q = softmax over g_s rows 0..C -> fp16 qh
    softmax_q<<<NROWS, 256>>>(sbuf, p_qh);

    // 4) scores = _q @ _k^T / sqrt(C)  (NT, K=4096)
    mma_gemm<<<dim3(C_/TN, C_/TM, B_), 256, SMEM_TOTAL>>>(
        p_qh, N_, sBCN,
        sbuf + (size_t)C_*N_, s2CN, nullptr, 0, N_,
        nullptr, 1.0f/sqrtf((float)C_), attn, (size_t)C_*C_, C_, C_,
        nullptr, 0, 0,
        nullptr, nullptr, nullptr, 0, 0, N_, 0);

    // 5) attn = softmax(scores) in-place + fp16 copy
    softmax_attn<<<NROWS, 128>>>(attn, p_at);

    // 6) y = attn @ v -> fp16 yh
    mma_gemm<<<dim3(N_/TN, C_/TM, B_), 256, SMEM_TOTAL>>>(
        p_at, C_, (size_t)C_*C_,
        qkvh + (size_t)2*C_*N_, s3CN, nullptr, 0, C_,
        nullptr, 1.f, nullptr, 0, 0, 0,
        yh, sBCN, 0,
        nullptr, nullptr, nullptr, 0, 0, C_, 1);

    // 7) gpre = Wg @ [y; x] + bg -> fp16 gph
    mma_gemm<<<dim3(N_/TN, C_/TM, B_), 256, SMEM_TOTAL>>>(
        wg, 2*C_, 0,
        yh, sBCN, xh, sBCN, C_,
        bg, 1.f, nullptr, 0, 0, 0,
        gph, sBCN, 0,
        nullptr, nullptr, nullptr, 0, 0, 2*C_, 1);

    // 8) r = Wr @ x + br ; out = y + sigmoid(gp)*(r - y)
    mma_gemm<<<dim3(N_/TN, C_/TM, B_), 256, SMEM_TOTAL>>>(
        wr, C_, 0,
        xh, sBCN, nullptr, 0, C_,
        br, 1.f, out, sBCN, N_, C_,
        nullptr, sBCN, 0,
        gph, yh, nullptr, 0, 1, C_, 1);
}

// round 11
// speedup vs baseline: 1.4620x; 1.1410x over previous
#include <cuda_runtime.h>
#include <cuda_fp16.h>
#include <math.h>
#include <stdint.h>
#include <stddef.h>

#define B_ 16
#define C_ 512
#define N_ 4096
#define NROWS (B_*C_)

#define TM 128
#define TN 128
#define TKC 32
#define NTHREADS 128                      // 4 warps, 2M x 2N, warp tile 64x64

#define A_PAD 40
#define B_PAD_T 136
#define AH_BYTES (128*40*2)               // 10240
#define BH_BYTES 10240                    // max(128*40*2, 32*136*2=8704)
#define STG_BYTES (AH_BYTES + BH_BYTES)   // 20480
#define NSTAGE 4
#define SMEM_TOTAL (NSTAGE*STG_BYTES)     // 81920 per CTA; 2 CTAs/SM

// ---------------- scratch (device globals, all fp16) ----------------
__device__ __half g_qkvh[(size_t)B_*3*C_*N_];
__device__ __half g_s  [(size_t)B_*2*C_*N_];    // {-relu(q*mq) | relu(k*mk)}
__device__ __half g_qh [(size_t)B_*C_*N_];
__device__ __half g_yh [(size_t)B_*C_*N_];
__device__ __half g_gph[(size_t)B_*C_*N_];
__device__ __half g_at [(size_t)B_*C_*C_];
__device__ __half g_xh [(size_t)B_*C_*N_];
__device__ __half g_wqkv[3*C_*C_];
__device__ __half g_wm[2*C_*C_];
__device__ __half g_wg[C_*2*C_];
__device__ __half g_wr[C_*C_];

// ---------------- PTX helpers ----------------
__device__ __forceinline__ void cpa16(uint32_t dst, const void* src){
    asm volatile("cp.async.cg.shared.global [%0], [%1], 16;"
                 :: "r"(dst), "l"(src) : "memory");
}
__device__ __forceinline__ void cp_commit(){
    asm volatile("cp.async.commit_group;" ::: "memory");
}
__device__ __forceinline__ void cp_wait2(){
    asm volatile("cp.async.wait_group 2;" ::: "memory");
}
__device__ __forceinline__ void cp_wait1(){
    asm volatile("cp.async.wait_group 1;" ::: "memory");
}
__device__ __forceinline__ void cp_wait0(){
    asm volatile("cp.async.wait_group 0;" ::: "memory");
}
__device__ __forceinline__ uint32_t smem_u32(const void* p){
    uint32_t a;
    asm("{ .reg .u64 t; cvta.to.shared.u64 t, %1; cvt.u32.u64 %0, t; }"
        : "=r"(a) : "l"(p));
    return a;
}
__device__ __forceinline__ void ldsm4(uint32_t* r, uint32_t addr){
    asm volatile("ldmatrix.sync.aligned.m8n8.x4.shared.b16 {%0,%1,%2,%3}, [%4];"
        : "=r"(r[0]), "=r"(r[1]), "=r"(r[2]), "=r"(r[3]) : "r"(addr));
}
__device__ __forceinline__ void ldsm2(uint32_t* r, uint32_t addr){
    asm volatile("ldmatrix.sync.aligned.m8n8.x2.shared.b16 {%0,%1}, [%2];"
        : "=r"(r[0]), "=r"(r[1]) : "r"(addr));
}
__device__ __forceinline__ void ldsm2t(uint32_t* r, uint32_t addr){
    asm volatile("ldmatrix.sync.aligned.m8n8.x2.trans.shared.b16 {%0,%1}, [%2];"
        : "=r"(r[0]), "=r"(r[1]) : "r"(addr));
}
__device__ __forceinline__ void mma16816(float* c, const uint32_t* a, const uint32_t* b){
    asm volatile(
        "mma.sync.aligned.m16n8k16.row.col.f32.f16.f16.f32 "
        "{%0,%1,%2,%3}, {%4,%5,%6,%7}, {%8,%9}, {%0,%1,%2,%3};"
        : "+f"(c[0]), "+f"(c[1]), "+f"(c[2]), "+f"(c[3])
        : "r"(a[0]), "r"(a[1]), "r"(a[2]), "r"(a[3]), "r"(b[0]), "r"(b[1]));
}
__device__ __forceinline__ uint32_t pack_h2(float x, float y){
    __half2 p(__float2half_rn(x), __float2half_rn(y));
    return *(uint32_t*)&p;
}
__device__ __forceinline__ float2 unpack_h2(uint32_t u){
    __half2 p = *(__half2*)&u;
    return make_float2(__half2float(p.x), __half2float(p.y));
}

// ---------------------------------------------------------------------------
// Pure fp16 GEMM. CTA 128x128, 4 warps (2Mx2N), warp tile 64x64,
// TKC=32, 4-stage cp.async pipeline, 2 CTAs/SM.
//   val = scale * sum_k A[m,k] * B[k,n] + bias[m]
// epiMode 0: fp32 Y rows m<y32Max; fp16 Yh rows >= yhOff.
// epiMode 1: Y(fp32) = Ey + sigmoid(Egp)*(val - Ey), Egp/Ey fp16.
// epiMode 2: prod = val * Eq[m,n];  Yh = (m<C_) ? -relu(prod) : relu(prod).
// ---------------------------------------------------------------------------
__global__ void __launch_bounds__(NTHREADS, 2) mma_gemm(
    const __half* __restrict__ Ah, int lda, size_t aBatch,
    const __half* __restrict__ B1, size_t b1B,
    const __half* __restrict__ B2, size_t b2B, int K1,
    const float* __restrict__ bias, float scale,
    float* __restrict__ Y, size_t yB, int yStride, int y32Max,
    __half* __restrict__ Yh, size_t yhB, int yhOff,
    const __half* __restrict__ Egp, const __half* __restrict__ Ey,
    const __half* __restrict__ Eq, size_t eqB, int epiMode,
    int K, int transB)
{
    extern __shared__ char smem[];
    const uint32_t sbase = smem_u32(smem);

    const int tid  = threadIdx.x;
    const int lane = tid & 31;
    const int wid  = tid >> 5;       // 0..3
    const int wm   = wid & 1;        // M strip (64)
    const int wn   = wid >> 1;       // N strip (64)
    const int b    = blockIdx.z;
    const int m0   = blockIdx.y * TM;
    const int n0   = blockIdx.x * TN;

    const __half* Ab = Ah + (size_t)b * aBatch;
    const int NC = K / TKC;

    auto load_stage = [&](int s, int kc){
        const uint32_t sa = sbase + s * STG_BYTES;
        // A: 128 rows x 32 halves = 512 x 16B -> 4 iters of 128 threads
        #pragma unroll
        for (int it = 0; it < 4; it++){
            int slot = it * NTHREADS + tid;
            int row = slot >> 2, c8 = (slot & 3) << 3;
            size_t go = (size_t)(m0 + row) * lda + kc * TKC + c8;
            cpa16(sa + 2 * (row * A_PAD + c8), Ab + go);
        }
        const uint32_t sb = sa + AH_BYTES;
        if (transB){
            // 32 k-rows x 128 n = 512 x 16B
            #pragma unroll
            for (int it = 0; it < 4; it++){
                int slot = it * NTHREADS + tid;
                int k = slot >> 4, n8 = (slot & 15) << 3;
                int kg = kc * TKC + k;
                const __half* src = (kg < K1)
                    ? (B1 + (size_t)b * b1B + (size_t)kg * N_ + n0 + n8)
                    : (B2 + (size_t)b * b2B + (size_t)(kg - K1) * N_ + n0 + n8);
                cpa16(sb + 2 * (k * B_PAD_T + n8), src);
            }
        } else {
            // 128 n-rows x 32 k = 512 x 16B
            #pragma unroll
            for (int it = 0; it < 4; it++){
                int slot = it * NTHREADS + tid;
                int n = slot >> 2, k8 = (slot & 3) << 3;
                size_t go = (size_t)b * b1B + (size_t)(n0 + n) * N_ + kc * TKC + k8;
                cpa16(sb + 2 * (n * A_PAD + k8), B1 + go);
            }
        }
        cp_commit();
    };

    float acc[4][8][4];
    #pragma unroll
    for (int i = 0; i < 4; i++)
        #pragma unroll
        for (int j = 0; j < 8; j++)
            #pragma unroll
            for (int r = 0; r < 4; r++) acc[i][j][r] = 0.f;

    const int a_lrow = lane & 15;
    const int a_lcol = (lane >> 4) << 3;
    const int bl_    = lane & 15;

    load_stage(0, 0);
    if (NC > 1) load_stage(1, 1);
    if (NC > 2) load_stage(2, 2);

    for (int kc = 0; kc < NC; kc++){
        int pend = (NC - kc > 3) ? 3 : (NC - kc);
        if (pend == 3) cp_wait2();
        else if (pend == 2) cp_wait1();
        else cp_wait0();
        __syncthreads();

        const uint32_t sa = sbase + (kc % NSTAGE) * STG_BYTES;
        const uint32_t sb = sa + AH_BYTES;

        #pragma unroll
        for (int ks = 0; ks < 2; ks++){
            uint32_t ah[4][4], bb[8][2];
            #pragma unroll
            for (int mt = 0; mt < 4; mt++){
                uint32_t ad = sa + 2 * ((wm*64 + mt*16 + a_lrow) * A_PAD + ks*16 + a_lcol);
                ldsm4(ah[mt], ad);
            }
            #pragma unroll
            for (int nt = 0; nt < 8; nt++){
                if (transB){
                    uint32_t bd = sb + 2 * ((ks*16 + bl_) * B_PAD_T + wn*64 + nt*8);
                    ldsm2t(bb[nt], bd);
                } else {
                    uint32_t bd = sb + 2 * ((wn*64 + nt*8 + (bl_ & 7)) * A_PAD + ks*16 + ((bl_ >> 3) << 3));
                    ldsm2(bb[nt], bd);
                }
            }
            #pragma unroll
            for (int mt = 0; mt < 4; mt++)
                #pragma unroll
                for (int nt = 0; nt < 8; nt++)
                    mma16816(acc[mt][nt], ah[mt], bb[nt]);
        }
        if (kc + 3 < NC) load_stage((kc + 3) % NSTAGE, kc + 3);
    }

    // ---- epilogue ----
    const int g = lane >> 2;
    const int t = lane & 3;
    #pragma unroll
    for (int mt = 0; mt < 4; mt++){
        int m = m0 + wm*64 + mt*16 + g;
        float bi_lo = bias ? bias[m]     : 0.f;
        float bi_hi = bias ? bias[m + 8] : 0.f;
        #pragma unroll
        for (int nt = 0; nt < 8; nt++){
            int nn = n0 + wn*64 + nt*8 + 2*t;
            float v00 = acc[mt][nt][0] * scale + bi_lo;
            float v01 = acc[mt][nt][1] * scale + bi_lo;
            float v10 = acc[mt][nt][2] * scale + bi_hi;
            float v11 = acc[mt][nt][3] * scale + bi_hi;

            if (epiMode == 1){
                size_t eo0 = (size_t)b * yhB + (size_t)m * N_ + nn;
                size_t eo1 = eo0 + (size_t)8 * N_;
                float2 gp0 = unpack_h2(*(const uint32_t*)(Egp + eo0));
                float2 gp1 = unpack_h2(*(const uint32_t*)(Egp + eo1));
                float2 y0  = unpack_h2(*(const uint32_t*)(Ey + eo0));
                float2 y1  = unpack_h2(*(const uint32_t*)(Ey + eo1));
                float s0 = 1.f/(1.f+__expf(-gp0.x));
                float s1 = 1.f/(1.f+__expf(-gp0.y));
                float s2 = 1.f/(1.f+__expf(-gp1.x));
                float s3 = 1.f/(1.f+__expf(-gp1.y));
                size_t off0 = (size_t)b * yB + (size_t)m * yStride + nn;
                size_t off1 = off0 + (size_t)8 * yStride;
                float2 o0, o1;
                o0.x = y0.x + s0 * (v00 - y0.x);
                o0.y = y0.y + s1 * (v01 - y0.y);
                o1.x = y1.x + s2 * (v10 - y1.x);
                o1.y = y1.y + s3 * (v11 - y1.y);
                *(float2*)(Y + off0) = o0;
                *(float2*)(Y + off1) = o1;
            } else if (epiMode == 2){
                size_t qo0 = (size_t)b * eqB + (size_t)m * N_ + nn;
                size_t qo1 = qo0 + (size_t)8 * N_;
                float2 q0 = unpack_h2(*(const uint32_t*)(Eq + qo0));
                float2 q1 = unpack_h2(*(const uint32_t*)(Eq + qo1));
                float p00 = v00 * q0.x, p01 = v01 * q0.y;
                float p10 = v10 * q1.x, p11 = v11 * q1.y;
                bool neg0 = (m < C_), neg1 = (m + 8 < C_);
                p00 = neg0 ? -fmaxf(p00, 0.f) : fmaxf(p00, 0.f);
                p01 = neg0 ? -fmaxf(p01, 0.f) : fmaxf(p01, 0.f);
                p10 = neg1 ? -fmaxf(p10, 0.f) : fmaxf(p10, 0.f);
                p11 = neg1 ? -fmaxf(p11, 0.f) : fmaxf(p11, 0.f);
                size_t so0 = (size_t)b * yhB + (size_t)m * N_ + nn;
                size_t so1 = so0 + (size_t)8 * N_;
                *(uint32_t*)(Yh + so0) = pack_h2(p00, p01);
                *(uint32_t*)(Yh + so1) = pack_h2(p10, p11);
            } else {
                if (Y && m < y32Max){
                    size_t off0 = (size_t)b * yB + (size_t)m * yStride + nn;
                    size_t off1 = off0 + (size_t)8 * yStride;
                    float2 o0 = {v00, v01}, o1 = {v10, v11};
                    *(float2*)(Y + off0) = o0;
                    *(float2*)(Y + off1) = o1;
                }
                if (Yh && m >= yhOff){
                    size_t so0 = (size_t)b * yhB + (size_t)(m - yhOff) * N_ + nn;
                    size_t so1 = so0 + (size_t)8 * N_;
                    *(uint32_t*)(Yh + so0) = pack_h2(v00, v01);
                    *(uint32_t*)(Yh + so1) = pack_h2(v10, v11);
                }
            }
        }
    }
}

// ---------------------------------------------------------------------------
// Fused fp32->fp16 conversion of all weights + x (one launch).
// ---------------------------------------------------------------------------
#define CVT_N0 (3*C_*C_)
#define CVT_N1 (2*C_*C_)
#define CVT_N2 (2*C_*C_)
#define CVT_N3 (C_*C_)
#define CVT_N4 (B_*C_*N_)
#define CVT_TOTAL (CVT_N0+CVT_N1+CVT_N2+CVT_N3+CVT_N4)

__global__ void conv_all(const float* __restrict__ s0, __half* __restrict__ d0,
                         const float* __restrict__ s1, __half* __restrict__ d1,
                         const float* __restrict__ s2, __half* __restrict__ d2,
                         const float* __restrict__ s3, __half* __restrict__ d3,
                         const float* __restrict__ s4, __half* __restrict__ d4)
{
    int i = blockIdx.x * 256 + threadIdx.x;
    if (i >= CVT_TOTAL) return;
    const float* s; __half* d; int off;
    if (i < CVT_N0){ s = s0; d = d0; off = i; }
    else if (i < CVT_N0+CVT_N1){ s = s1; d = d1; off = i - CVT_N0; }
    else if (i < CVT_N0+CVT_N1+CVT_N2){ s = s2; d = d2; off = i - CVT_N0 - CVT_N1; }
    else if (i < CVT_N0+CVT_N1+CVT_N2+CVT_N3){ s = s3; d = d3; off = i - CVT_N0 - CVT_N1 - CVT_N2; }
    else { s = s4; d = d4; off = i - CVT_N0 - CVT_N1 - CVT_N2 - CVT_N3; }
    d[off] = __float2half_rn(s[off]);
}

// ---------------------------------------------------------------------------
__global__ void softmax_q(const __half* __restrict__ tbuf, __half* __restrict__ qh)
{
    __shared__ float red[8];
    __shared__ float bc;
    const int row = blockIdx.x;
    const int b = row >> 9, c = row & 511;
    const uint32_t* src = (const uint32_t*)(tbuf + ((size_t)b*1024 + c) * (size_t)N_);
    uint32_t* dst = (uint32_t*)(qh + (size_t)row * N_);

    float v[16];
    float mx = -1e30f;
    #pragma unroll
    for (int i = 0; i < 8; i++){
        int idx = threadIdx.x + (i << 8);
        float2 f = unpack_h2(src[idx]);
        v[2*i]   = f.x;
        v[2*i+1] = f.y;
        mx = fmaxf(mx, fmaxf(f.x, f.y));
    }
    #pragma unroll
    for (int off = 16; off; off >>= 1)
        mx = fmaxf(mx, __shfl_xor_sync(0xffffffffu, mx, off));
    if ((threadIdx.x & 31) == 0) red[threadIdx.x >> 5] = mx;
    __syncthreads();
    if (threadIdx.x == 0){
        float tv = red[0];
        #pragma unroll
        for (int i = 1; i < 8; i++) tv = fmaxf(tv, red[i]);
        bc = tv;
    }
    __syncthreads();
    mx = bc;

    float sm = 0.f;
    #pragma unroll
    for (int i = 0; i < 16; i++){
        v[i] = __expf(v[i] - mx);
        sm += v[i];
    }
    #pragma unroll
    for (int off = 16; off; off >>= 1)
        sm += __shfl_xor_sync(0xffffffffu, sm, off);
    __syncthreads();
    if ((threadIdx.x & 31) == 0) red[threadIdx.x >> 5] = sm;
    __syncthreads();
    if (threadIdx.x == 0){
        float tv = 0.f;
        #pragma unroll
        for (int i = 0; i < 8; i++) tv += red[i];
        bc = tv;
    }
    __syncthreads();
    const float rinv = 1.f / bc;
    #pragma unroll
    for (int i = 0; i < 8; i++){
        int idx = threadIdx.x + (i << 8);
        dst[idx] = pack_h2(v[2*i] * rinv, v[2*i+1] * rinv);
    }
}

// ---------------------------------------------------------------------------
__global__ void softmax_attn(float* __restrict__ S, __half* __restrict__ ah)
{
    __shared__ float red[4];
    __shared__ float bc;
    const int row = blockIdx.x;
    float* p = S + (size_t)row * 512;
    const size_t base = (size_t)row * 512;

    float v[4];
    float mx = -1e30f;
    #pragma unroll
    for (int i = 0; i < 4; i++){
        int idx = threadIdx.x + (i << 7);
        v[i] = p[idx];
        mx = fmaxf(mx, v[i]);
    }
    #pragma unroll
    for (int off = 16; off; off >>= 1)
        mx = fmaxf(mx, __shfl_xor_sync(0xffffffffu, mx, off));
    if ((threadIdx.x & 31) == 0) red[threadIdx.x >> 5] = mx;
    __syncthreads();
    if (threadIdx.x == 0)
        bc = fmaxf(fmaxf(red[0], red[1]), fmaxf(red[2], red[3]));
    __syncthreads();
    mx = bc;

    float sm = 0.f;
    #pragma unroll
    for (int i = 0; i < 4; i++){
        v[i] = __expf(v[i] - mx);
        sm += v[i];
    }
    #pragma unroll
    for (int off = 16; off; off >>= 1)
        sm += __shfl_xor_sync(0xffffffffu, sm, off);
    __syncthreads();
    if ((threadIdx.x & 31) == 0) red[threadIdx.x >> 5] = sm;
    __syncthreads();
    if (threadIdx.x == 0) bc = red[0] + red[1] + red[2] + red[3];
    __syncthreads();
    const float rinv = 1.f / bc;
    #pragma unroll
    for (int i = 0; i < 4; i++){
        int idx = threadIdx.x + (i << 7);
        float f = v[i] * rinv;
        p[idx] = f;
        ah[base + idx] = __float2half_rn(f);
    }
}

// ---------------------------------------------------------------------------
extern "C" void kernel_launch(void* const* d_in, const int* in_sizes, int n_in,
                              void* d_out, int out_size)
{
    const float* x    = (const float*)d_in[0];
    const float* Wqkv = (const float*)d_in[1];
    const float* bqkv = (const float*)d_in[2];
    const float* Wm   = (const float*)d_in[3];
    const float* bm   = (const float*)d_in[4];
    const float* Wg   = (const float*)d_in[5];
    const float* bg   = (const float*)d_in[6];
    const float* Wr   = (const float*)d_in[7];
    const float* br   = (const float*)d_in[8];

    float* out  = (float*)d_out;
    float* attn = out + (size_t)B_ * C_ * N_;

    cudaFuncSetAttribute(mma_gemm, cudaFuncAttributeMaxDynamicSharedMemorySize, SMEM_TOTAL);

    __half *qkvh, *sbuf, *p_qh, *yh, *gph, *p_at, *xh;
    __half *wqkv, *wm, *wg, *wr;
    cudaGetSymbolAddress((void**)&qkvh, g_qkvh);
    cudaGetSymbolAddress((void**)&sbuf, g_s);
    cudaGetSymbolAddress((void**)&p_qh, g_qh);
    cudaGetSymbolAddress((void**)&yh,   g_yh);
    cudaGetSymbolAddress((void**)&gph,  g_gph);
    cudaGetSymbolAddress((void**)&p_at, g_at);
    cudaGetSymbolAddress((void**)&xh,   g_xh);
    cudaGetSymbolAddress((void**)&wqkv, g_wqkv);
    cudaGetSymbolAddress((void**)&wm,   g_wm);
    cudaGetSymbolAddress((void**)&wg,   g_wg);
    cudaGetSymbolAddress((void**)&wr,   g_wr);

    const size_t sBCN = (size_t)C_ * N_;
    const size_t s3CN = (size_t)3*C_ * N_;
    const size_t s2CN = (size_t)2*C_ * N_;

    // 0) convert all weights + x to fp16 (one launch)
    conv_all<<<(CVT_TOTAL + 255)/256, 256>>>(
        Wqkv, wqkv, Wm, wm, Wg, wg, Wr, wr, x, xh);

    // 1) qkv = Wqkv @ x + bqkv  -> all fp16
    mma_gemm<<<dim3(N_/TN, 3*C_/TM, B_), NTHREADS, SMEM_TOTAL>>>(
        wqkv, C_, 0,
        xh, sBCN, nullptr, 0, C_,
        bqkv, 1.f, nullptr, 0, 0, 0,
        qkvh, s3CN, 0,
        nullptr, nullptr, nullptr, 0, 0, C_, 1);

    // 2) mqk = Wm @ v + bm ; epilogue 2 -> g_s = {-relu(q*mq) | relu(k*mk)}
    mma_gemm<<<dim3(N_/TN, 2*C_/TM, B_), NTHREADS, SMEM_TOTAL>>>(
        wm, C_, 0,
        qkvh + (size_t)2*C_*N_, s3CN, nullptr, 0, C_,
        bm, 1.f, nullptr, 0, 0, 0,
        sbuf, s2CN, 0,
        nullptr, nullptr, qkvh, s3CN, 2, C_, 1);

    // 3) _q = softmax over g_s rows 0..C -> fp16 qh
    softmax_q<<<NROWS, 256>>>(sbuf, p_qh);

    // 4) scores = _q @ _k^T / sqrt(C)  (NT, K=4096)
    mma_gemm<<<dim3(C_/TN, C_/TM, B_), NTHREADS, SMEM_TOTAL>>>(
        p_qh, N_, sBCN,
        sbuf + (size_t)C_*N_, s2CN, nullptr, 0, N_,
        nullptr, 1.0f/sqrtf((float)C_), attn, (size_t)C_*C_, C_, C_,
        nullptr, 0, 0,
        nullptr, nullptr, nullptr, 0, 0, N_, 0);

    // 5) attn = softmax(scores) in-place + fp16 copy
    softmax_attn<<<NROWS, 128>>>(attn, p_at);

    // 6) y = attn @ v -> fp16 yh
    mma_gemm<<<dim3(N_/TN, C_/TM, B_), NTHREADS, SMEM_TOTAL>>>(
        p_at, C_, (size_t)C_*C_,
        qkvh + (size_t)2*C_*N_, s3CN, nullptr, 0, C_,
        nullptr, 1.f, nullptr, 0, 0, 0,
        yh, sBCN, 0,
        nullptr, nullptr, nullptr, 0, 0, C_, 1);

    // 7) gpre = Wg @ [y; x] + bg -> fp16 gph
    mma_gemm<<<dim3(N_/TN, C_/TM, B_), NTHREADS, SMEM_TOTAL>>>(
        wg, 2*C_, 0,
        yh, sBCN, xh, sBCN, C_,
        bg, 1.f, nullptr, 0, 0, 0,
        gph, sBCN, 0,
        nullptr, nullptr, nullptr, 0, 0, 2*C_, 1);

    // 8) r = Wr @ x + br ; out = y + sigmoid(gp)*(r - y)
    mma_gemm<<<dim3(N_/TN, C_/TM, B_), NTHREADS, SMEM_TOTAL>>>(
        wr, C_, 0,
        xh, sBCN, nullptr, 0, C_,
        br, 1.f, out, sBCN, N_, C_,
        nullptr, sBCN, 0,
        gph, yh, nullptr, 0, 1, C_, 1);
}